// round 5
// baseline (speedup 1.0000x reference)
#include <cuda_runtime.h>

// cos(pi*t/16) constants
#define CC1 0.98078528040323044913f
#define CC2 0.92387953251128675613f
#define CC3 0.83146961230254523708f
#define CC4 0.70710678118654752440f
#define CC5 0.55557023301960222474f
#define CC6 0.38268343236508977173f
#define CC7 0.19509032201612826785f

typedef unsigned long long u64;

__device__ __forceinline__ u64 pack2(float lo, float hi) {
    u64 r; asm("mov.b64 %0, {%1, %2};" : "=l"(r) : "f"(lo), "f"(hi)); return r;
}
__device__ __forceinline__ void unpack2(u64 v, float& lo, float& hi) {
    asm("mov.b64 {%0, %1}, %2;" : "=f"(lo), "=f"(hi) : "l"(v));
}
__device__ __forceinline__ u64 add2(u64 a, u64 b) {
    u64 d; asm("add.rn.f32x2 %0, %1, %2;" : "=l"(d) : "l"(a), "l"(b)); return d;
}
__device__ __forceinline__ u64 mul2(u64 a, u64 b) {
    u64 d; asm("mul.rn.f32x2 %0, %1, %2;" : "=l"(d) : "l"(a), "l"(b)); return d;
}
__device__ __forceinline__ u64 fma2(u64 a, u64 b, u64 c) {
    u64 d; asm("fma.rn.f32x2 %0, %1, %2, %3;" : "=l"(d) : "l"(a), "l"(b), "l"(c)); return d;
}

// Horizontal pass: forward masked DCT coefficients + inverse, in place.
// A rows are distributed: this lane holds columns {2q, 2q+1}. Per kept coeff:
// local partial (mul+fma), 4-lane all-reduce (2x shfl_xor), back-substitute.
// Scale: result is 4x the true horizontal round-trip (folded into stage 3).
template <int NR>
__device__ __forceinline__ void hpass(float (&A)[NR][2],
                                      const unsigned (&mask)[NR],
                                      const float (&Wl)[6][2])
{
#pragma unroll
    for (int k = 0; k < NR; ++k) {
        const unsigned m = mask[k];
        float Bv[6];
#pragma unroll
        for (int l = 0; l < 6; ++l) {
            if ((m >> l) & 1) {
                float p = (l == 0) ? (A[k][0] + A[k][1])
                                   : fmaf(A[k][1], Wl[l][1], A[k][0] * Wl[l][0]);
                p += __shfl_xor_sync(0xffffffffu, p, 1);
                p += __shfl_xor_sync(0xffffffffu, p, 2);
                Bv[l] = p;
            }
        }
#pragma unroll
        for (int jj = 0; jj < 2; ++jj) {
            float s = 0.f;
#pragma unroll
            for (int l = 0; l < 6; ++l)
                if ((m >> l) & 1)
                    s = fmaf(Bv[l], (l == 0) ? 0.5f : Wl[l][jj], s);
            A[k][jj] = s;
        }
    }
}

// Four threads per 8x8 tile, lane q owns columns {2q, 2q+1} (one f32x2).
// Luma split: out_c = T9(x_c) + DeltaT16(y), y = .299R+.587G+.114B.
// T9: per-channel masked DCT round trip keeping rows 0-2, prefix {4,3,2}.
// DeltaT16: luma round trip keeping Y-mask minus UV-mask (16 coeffs, rows 0-6).
// No output color conversion (YUV2RGB column 0 is exactly (1,1,1)).
__global__ void __launch_bounds__(128, 6)
jpeg_fused_kernel(const float* __restrict__ in, float* __restrict__ out, int nthr)
{
    const int g = blockIdx.x * blockDim.x + threadIdx.x;
    if (g >= nthr) return;
    const int tile = g >> 2;
    const int q = g & 3;

    // D[k][n] = cos(pi/8 * (n+0.5) * k)
    const float D[8][8] = {
        { 1.f,  1.f,  1.f,  1.f,  1.f,  1.f,  1.f,  1.f},
        { CC1,  CC3,  CC5,  CC7, -CC7, -CC5, -CC3, -CC1},
        { CC2,  CC6, -CC6, -CC2, -CC2, -CC6,  CC6,  CC2},
        { CC3, -CC7, -CC1, -CC5,  CC5,  CC1,  CC7, -CC3},
        { CC4, -CC4, -CC4,  CC4,  CC4, -CC4, -CC4,  CC4},
        { CC5, -CC1,  CC7,  CC3, -CC3, -CC7,  CC1, -CC5},
        { CC6, -CC2,  CC2, -CC6, -CC6,  CC2, -CC2,  CC6},
        { CC7, -CC5,  CC3, -CC1,  CC1, -CC3,  CC5, -CC7}
    };

    // kept-coefficient bitmasks per row (bit l = horizontal coeff l kept)
    const unsigned MRGB[3] = {0x0Fu, 0x07u, 0x03u};                    // 9 coeffs
    const unsigned MY[7]   = {0x30u, 0x18u, 0x0Cu, 0x0Fu, 0x07u, 0x03u, 0x01u}; // 16

    // Lane-dependent horizontal constants Wl[l][jj] = D[l][2q+jj], l=1..5.
    float Wl[6][2];
#pragma unroll
    for (int l = 1; l < 6; ++l) {
        Wl[l][0] = (q & 2) ? ((q & 1) ? D[l][6] : D[l][4])
                           : ((q & 1) ? D[l][2] : D[l][0]);
        Wl[l][1] = (q & 2) ? ((q & 1) ? D[l][7] : D[l][5])
                           : ((q & 1) ? D[l][3] : D[l][1]);
    }

    // packed constants
    const u64 CR   = pack2(0.299f, 0.299f);
    const u64 CG   = pack2(0.587f, 0.587f);
    const u64 CB   = pack2(0.114f, 0.114f);
    const u64 MIN1 = pack2(-1.f, -1.f);

    const int W = 512;
    const int S = 512 * 512;

    const int b  = tile >> 12;
    const int t  = tile & 4095;
    const int ty = t >> 6;
    const int tx = t & 63;

    const size_t base = (size_t)b * (3 * S) + (size_t)(ty * 8) * W
                      + (size_t)(tx * 8) + (size_t)(q * 2);
    const float* pr = in + base;
    const float* pg = pr + S;
    const float* pb = pg + S;

    float AY[7][2];
    float AR[3][2], AG[3][2], AB[3][2];
#pragma unroll
    for (int k = 0; k < 7; ++k) { AY[k][0] = 0.f; AY[k][1] = 0.f; }
#pragma unroll
    for (int k = 0; k < 3; ++k) {
        AR[k][0] = 0.f; AR[k][1] = 0.f;
        AG[k][0] = 0.f; AG[k][1] = 0.f;
        AB[k][0] = 0.f; AB[k][1] = 0.f;
    }

    // ---- stage 1: load row pairs (p, 7-p), packed s/d, packed luma,
    //      vertical DCT accumulate (RGB rows 0-2, luma rows 0-6) ----
#pragma unroll
    for (int p = 0; p < 4; ++p) {
        const int n2 = 7 - p;
        u64 ra = *(const u64*)(pr + p  * W);
        u64 rb = *(const u64*)(pr + n2 * W);
        u64 sr = add2(ra, rb), dr = fma2(rb, MIN1, ra);
        u64 ga = *(const u64*)(pg + p  * W);
        u64 gb = *(const u64*)(pg + n2 * W);
        u64 sg = add2(ga, gb), dg = fma2(gb, MIN1, ga);
        u64 ba = *(const u64*)(pb + p  * W);
        u64 bb = *(const u64*)(pb + n2 * W);
        u64 sb = add2(ba, bb), db = fma2(bb, MIN1, ba);

        // luma of s and d (linearity: luma commutes with +/-)
        u64 sy = fma2(sr, CR, fma2(sg, CG, mul2(sb, CB)));
        u64 dy = fma2(dr, CR, fma2(dg, CG, mul2(db, CB)));

        float srf[2], drf[2], sgf[2], dgf[2], sbf[2], dbf[2], syf[2], dyf[2];
        unpack2(sr, srf[0], srf[1]); unpack2(dr, drf[0], drf[1]);
        unpack2(sg, sgf[0], sgf[1]); unpack2(dg, dgf[0], dgf[1]);
        unpack2(sb, sbf[0], sbf[1]); unpack2(db, dbf[0], dbf[1]);
        unpack2(sy, syf[0], syf[1]); unpack2(dy, dyf[0], dyf[1]);

#pragma unroll
        for (int jj = 0; jj < 2; ++jj) {
            // RGB channels: rows 0 (sum), 2 (even), 1 (odd)
            AR[0][jj] += srf[jj];
            AR[2][jj] = fmaf(D[2][p], srf[jj], AR[2][jj]);
            AR[1][jj] = fmaf(D[1][p], drf[jj], AR[1][jj]);
            AG[0][jj] += sgf[jj];
            AG[2][jj] = fmaf(D[2][p], sgf[jj], AG[2][jj]);
            AG[1][jj] = fmaf(D[1][p], dgf[jj], AG[1][jj]);
            AB[0][jj] += sbf[jj];
            AB[2][jj] = fmaf(D[2][p], sbf[jj], AB[2][jj]);
            AB[1][jj] = fmaf(D[1][p], dbf[jj], AB[1][jj]);
            // luma: rows 0-6
            AY[0][jj] += syf[jj];
            AY[2][jj] = fmaf(D[2][p], syf[jj], AY[2][jj]);
            AY[4][jj] = fmaf(D[4][p], syf[jj], AY[4][jj]);
            AY[6][jj] = fmaf(D[6][p], syf[jj], AY[6][jj]);
            AY[1][jj] = fmaf(D[1][p], dyf[jj], AY[1][jj]);
            AY[3][jj] = fmaf(D[3][p], dyf[jj], AY[3][jj]);
            AY[5][jj] = fmaf(D[5][p], dyf[jj], AY[5][jj]);
        }
    }

    // ---- stage 2: horizontal masked round trip per unit ----
    hpass<3>(AR, MRGB, Wl);
    hpass<3>(AG, MRGB, Wl);
    hpass<3>(AB, MRGB, Wl);
    hpass<7>(AY, MY,   Wl);

    // ---- stage 3: vertical inverse (weights k==0 -> 0.03125, else 0.0625*D[k][n])
    //      out_c = idct(A_c) + idct(AY); coalesced stores ----
    float* qr = out + base;
    float* qg = qr + S;
    float* qb = qg + S;
#pragma unroll
    for (int p = 0; p < 4; ++p) {
        const int n2 = 7 - p;
        float rA[2], rB[2], gA[2], gB[2], bA[2], bB[2];
#pragma unroll
        for (int jj = 0; jj < 2; ++jj) {
            // luma part
            float ey = 0.03125f * AY[0][jj];
            ey = fmaf(0.0625f * D[2][p], AY[2][jj], ey);
            ey = fmaf(0.0625f * D[4][p], AY[4][jj], ey);
            ey = fmaf(0.0625f * D[6][p], AY[6][jj], ey);
            float oy = 0.0625f * D[1][p] * AY[1][jj];
            oy = fmaf(0.0625f * D[3][p], AY[3][jj], oy);
            oy = fmaf(0.0625f * D[5][p], AY[5][jj], oy);
            const float yA = ey + oy, yB = ey - oy;

            // R
            float e = 0.03125f * AR[0][jj];
            e = fmaf(0.0625f * D[2][p], AR[2][jj], e);
            float o = 0.0625f * D[1][p] * AR[1][jj];
            rA[jj] = (e + o) + yA;  rB[jj] = (e - o) + yB;
            // G
            e = 0.03125f * AG[0][jj];
            e = fmaf(0.0625f * D[2][p], AG[2][jj], e);
            o = 0.0625f * D[1][p] * AG[1][jj];
            gA[jj] = (e + o) + yA;  gB[jj] = (e - o) + yB;
            // B
            e = 0.03125f * AB[0][jj];
            e = fmaf(0.0625f * D[2][p], AB[2][jj], e);
            o = 0.0625f * D[1][p] * AB[1][jj];
            bA[jj] = (e + o) + yA;  bB[jj] = (e - o) + yB;
        }
        *(float2*)(qr + p  * W) = make_float2(rA[0], rA[1]);
        *(float2*)(qg + p  * W) = make_float2(gA[0], gA[1]);
        *(float2*)(qb + p  * W) = make_float2(bA[0], bA[1]);
        *(float2*)(qr + n2 * W) = make_float2(rB[0], rB[1]);
        *(float2*)(qg + n2 * W) = make_float2(gB[0], gB[1]);
        *(float2*)(qb + n2 * W) = make_float2(bB[0], bB[1]);
    }
}

extern "C" void kernel_launch(void* const* d_in, const int* in_sizes, int n_in,
                              void* d_out, int out_size)
{
    const float* in = (const float*)d_in[0];
    float* out = (float*)d_out;
    const int total = in_sizes[0];               // B*3*512*512
    const int B = total / (3 * 512 * 512);
    const int nthr = B * 64 * 64 * 4;            // 4 threads per tile
    const int threads = 128;
    const int blocks = (nthr + threads - 1) / threads;
    jpeg_fused_kernel<<<blocks, threads>>>(in, out, nthr);
}

// round 6
// speedup vs baseline: 1.0019x; 1.0019x over previous
#include <cuda_runtime.h>

// cos(pi*t/16) constants
#define CC1 0.98078528040323044913f
#define CC2 0.92387953251128675613f
#define CC3 0.83146961230254523708f
#define CC4 0.70710678118654752440f
#define CC5 0.55557023301960222474f
#define CC6 0.38268343236508977173f
#define CC7 0.19509032201612826785f

typedef unsigned long long u64;

__device__ __forceinline__ u64 pack2(float lo, float hi) {
    u64 r; asm("mov.b64 %0, {%1, %2};" : "=l"(r) : "f"(lo), "f"(hi)); return r;
}
__device__ __forceinline__ void unpack2(u64 v, float& lo, float& hi) {
    asm("mov.b64 {%0, %1}, %2;" : "=f"(lo), "=f"(hi) : "l"(v));
}
__device__ __forceinline__ u64 add2(u64 a, u64 b) {
    u64 d; asm("add.rn.f32x2 %0, %1, %2;" : "=l"(d) : "l"(a), "l"(b)); return d;
}
__device__ __forceinline__ u64 fma2(u64 a, u64 b, u64 c) {
    u64 d; asm("fma.rn.f32x2 %0, %1, %2, %3;" : "=l"(d) : "l"(a), "l"(b), "l"(c)); return d;
}

// Horizontal pass: forward masked DCT coefficients + inverse, in place.
// Lane holds columns {2q, 2q+1}; per kept coeff: local partial, 4-lane
// all-reduce (2x shfl_xor), back-substitute. Result is 4x true round trip
// (folded into stage-3 immediates).
template <int NR>
__device__ __forceinline__ void hpass(float (&A)[NR][2],
                                      const unsigned (&mask)[NR],
                                      const float (&Wl)[6][2])
{
#pragma unroll
    for (int k = 0; k < NR; ++k) {
        const unsigned m = mask[k];
        float Bv[6];
#pragma unroll
        for (int l = 0; l < 6; ++l) {
            if ((m >> l) & 1) {
                float p = (l == 0) ? (A[k][0] + A[k][1])
                                   : fmaf(A[k][1], Wl[l][1], A[k][0] * Wl[l][0]);
                p += __shfl_xor_sync(0xffffffffu, p, 1);
                p += __shfl_xor_sync(0xffffffffu, p, 2);
                Bv[l] = p;
            }
        }
#pragma unroll
        for (int jj = 0; jj < 2; ++jj) {
            float s = 0.f;
#pragma unroll
            for (int l = 0; l < 6; ++l)
                if ((m >> l) & 1)
                    s = fmaf(Bv[l], (l == 0) ? 0.5f : Wl[l][jj], s);
            A[k][jj] = s;
        }
    }
}

// Four threads per 8x8 tile, lane q owns columns {2q, 2q+1}.
// Luma split: out_c = T9(x_c) + DeltaT16(y), y = .299R+.587G+.114B;
// no output color conversion (YUV2RGB column 0 is exactly (1,1,1)).
__global__ void __launch_bounds__(128, 7)
jpeg_fused_kernel(const float* __restrict__ in, float* __restrict__ out, int nthr)
{
    const int g = blockIdx.x * blockDim.x + threadIdx.x;
    if (g >= nthr) return;
    const int tile = g >> 2;
    const int q = g & 3;

    // D[k][n] = cos(pi/8 * (n+0.5) * k)
    const float D[8][8] = {
        { 1.f,  1.f,  1.f,  1.f,  1.f,  1.f,  1.f,  1.f},
        { CC1,  CC3,  CC5,  CC7, -CC7, -CC5, -CC3, -CC1},
        { CC2,  CC6, -CC6, -CC2, -CC2, -CC6,  CC6,  CC2},
        { CC3, -CC7, -CC1, -CC5,  CC5,  CC1,  CC7, -CC3},
        { CC4, -CC4, -CC4,  CC4,  CC4, -CC4, -CC4,  CC4},
        { CC5, -CC1,  CC7,  CC3, -CC3, -CC7,  CC1, -CC5},
        { CC6, -CC2,  CC2, -CC6, -CC6,  CC2, -CC2,  CC6},
        { CC7, -CC5,  CC3, -CC1,  CC1, -CC3,  CC5, -CC7}
    };

    // kept-coefficient bitmasks per row (bit l = horizontal coeff l kept)
    const unsigned MRGB[3] = {0x0Fu, 0x07u, 0x03u};                              // 9
    const unsigned MY[7]   = {0x30u, 0x18u, 0x0Cu, 0x0Fu, 0x07u, 0x03u, 0x01u}; // 16

    // Lane-dependent horizontal constants Wl[l][jj] = D[l][2q+jj], l=1..5.
    float Wl[6][2];
#pragma unroll
    for (int l = 1; l < 6; ++l) {
        Wl[l][0] = (q & 2) ? ((q & 1) ? D[l][6] : D[l][4])
                           : ((q & 1) ? D[l][2] : D[l][0]);
        Wl[l][1] = (q & 2) ? ((q & 1) ? D[l][7] : D[l][5])
                           : ((q & 1) ? D[l][3] : D[l][1]);
    }

    const u64 MIN1 = pack2(-1.f, -1.f);

    const int W = 512;
    const int S = 512 * 512;

    const int b  = tile >> 12;
    const int t  = tile & 4095;
    const int ty = t >> 6;
    const int tx = t & 63;

    // single base pointer; channel offsets S, 2S become LDG/STG immediates
    const float* p0 = in + ((size_t)b * (3 * S) + (size_t)(ty * 8) * W
                      + (size_t)(tx * 8) + (size_t)(q * 2));
    float* o0 = out + ((size_t)b * (3 * S) + (size_t)(ty * 8) * W
                      + (size_t)(tx * 8) + (size_t)(q * 2));

    float AY[7][2];
    float AR[3][2], AG[3][2], AB[3][2];
#pragma unroll
    for (int k = 0; k < 7; ++k) { AY[k][0] = 0.f; AY[k][1] = 0.f; }
#pragma unroll
    for (int k = 0; k < 3; ++k) {
        AR[k][0] = 0.f; AR[k][1] = 0.f;
        AG[k][0] = 0.f; AG[k][1] = 0.f;
        AB[k][0] = 0.f; AB[k][1] = 0.f;
    }

    // ---- stage 1: row pairs (p, 7-p): packed s/d, scalar luma,
    //      vertical DCT accumulate (RGB rows 0-2, luma rows 0-6) ----
#pragma unroll
    for (int p = 0; p < 4; ++p) {
        const int i0 = p * W;
        const int i1 = (7 - p) * W;
        u64 sr, dr, sg, dg, sb, db;
        {
            u64 a = *(const u64*)(p0 + i0);
            u64 c = *(const u64*)(p0 + i1);
            sr = add2(a, c); dr = fma2(c, MIN1, a);
        }
        {
            u64 a = *(const u64*)(p0 + i0 + S);
            u64 c = *(const u64*)(p0 + i1 + S);
            sg = add2(a, c); dg = fma2(c, MIN1, a);
        }
        {
            u64 a = *(const u64*)(p0 + i0 + 2 * S);
            u64 c = *(const u64*)(p0 + i1 + 2 * S);
            sb = add2(a, c); db = fma2(c, MIN1, a);
        }
        float srf[2], drf[2], sgf[2], dgf[2], sbf[2], dbf[2];
        unpack2(sr, srf[0], srf[1]); unpack2(dr, drf[0], drf[1]);
        unpack2(sg, sgf[0], sgf[1]); unpack2(dg, dgf[0], dgf[1]);
        unpack2(sb, sbf[0], sbf[1]); unpack2(db, dbf[0], dbf[1]);

#pragma unroll
        for (int jj = 0; jj < 2; ++jj) {
            // scalar luma of s and d (FFMA-imm forms)
            float sy = fmaf(0.299f, srf[jj], fmaf(0.587f, sgf[jj], 0.114f * sbf[jj]));
            float dy = fmaf(0.299f, drf[jj], fmaf(0.587f, dgf[jj], 0.114f * dbf[jj]));
            // RGB channels: rows 0 (sum), 2 (even), 1 (odd)
            AR[0][jj] += srf[jj];
            AR[2][jj] = fmaf(D[2][p], srf[jj], AR[2][jj]);
            AR[1][jj] = fmaf(D[1][p], drf[jj], AR[1][jj]);
            AG[0][jj] += sgf[jj];
            AG[2][jj] = fmaf(D[2][p], sgf[jj], AG[2][jj]);
            AG[1][jj] = fmaf(D[1][p], dgf[jj], AG[1][jj]);
            AB[0][jj] += sbf[jj];
            AB[2][jj] = fmaf(D[2][p], sbf[jj], AB[2][jj]);
            AB[1][jj] = fmaf(D[1][p], dbf[jj], AB[1][jj]);
            // luma: rows 0-6
            AY[0][jj] += sy;
            AY[2][jj] = fmaf(D[2][p], sy, AY[2][jj]);
            AY[4][jj] = fmaf(D[4][p], sy, AY[4][jj]);
            AY[6][jj] = fmaf(D[6][p], sy, AY[6][jj]);
            AY[1][jj] = fmaf(D[1][p], dy, AY[1][jj]);
            AY[3][jj] = fmaf(D[3][p], dy, AY[3][jj]);
            AY[5][jj] = fmaf(D[5][p], dy, AY[5][jj]);
        }
    }

    // ---- stage 2: horizontal masked round trip per unit ----
    hpass<3>(AR, MRGB, Wl);
    hpass<3>(AG, MRGB, Wl);
    hpass<3>(AB, MRGB, Wl);
    hpass<7>(AY, MY,   Wl);

    // ---- stage 3: vertical inverse (k==0 -> 0.03125, else 0.0625*D[k][n]);
    //      out_c = idct(A_c) + idct(AY); coalesced stores ----
#pragma unroll
    for (int p = 0; p < 4; ++p) {
        const int i0 = p * W;
        const int i1 = (7 - p) * W;
        float rA[2], rB[2], gA[2], gB[2], bA[2], bB[2];
#pragma unroll
        for (int jj = 0; jj < 2; ++jj) {
            // luma part
            float ey = 0.03125f * AY[0][jj];
            ey = fmaf(0.0625f * D[2][p], AY[2][jj], ey);
            ey = fmaf(0.0625f * D[4][p], AY[4][jj], ey);
            ey = fmaf(0.0625f * D[6][p], AY[6][jj], ey);
            float oy = 0.0625f * D[1][p] * AY[1][jj];
            oy = fmaf(0.0625f * D[3][p], AY[3][jj], oy);
            oy = fmaf(0.0625f * D[5][p], AY[5][jj], oy);
            const float yA = ey + oy, yB = ey - oy;

            float e = 0.03125f * AR[0][jj];
            e = fmaf(0.0625f * D[2][p], AR[2][jj], e);
            float o = 0.0625f * D[1][p] * AR[1][jj];
            rA[jj] = (e + o) + yA;  rB[jj] = (e - o) + yB;

            e = 0.03125f * AG[0][jj];
            e = fmaf(0.0625f * D[2][p], AG[2][jj], e);
            o = 0.0625f * D[1][p] * AG[1][jj];
            gA[jj] = (e + o) + yA;  gB[jj] = (e - o) + yB;

            e = 0.03125f * AB[0][jj];
            e = fmaf(0.0625f * D[2][p], AB[2][jj], e);
            o = 0.0625f * D[1][p] * AB[1][jj];
            bA[jj] = (e + o) + yA;  bB[jj] = (e - o) + yB;
        }
        *(float2*)(o0 + i0)         = make_float2(rA[0], rA[1]);
        *(float2*)(o0 + i0 + S)     = make_float2(gA[0], gA[1]);
        *(float2*)(o0 + i0 + 2 * S) = make_float2(bA[0], bA[1]);
        *(float2*)(o0 + i1)         = make_float2(rB[0], rB[1]);
        *(float2*)(o0 + i1 + S)     = make_float2(gB[0], gB[1]);
        *(float2*)(o0 + i1 + 2 * S) = make_float2(bB[0], bB[1]);
    }
}

extern "C" void kernel_launch(void* const* d_in, const int* in_sizes, int n_in,
                              void* d_out, int out_size)
{
    const float* in = (const float*)d_in[0];
    float* out = (float*)d_out;
    const int total = in_sizes[0];               // B*3*512*512
    const int B = total / (3 * 512 * 512);
    const int nthr = B * 64 * 64 * 4;            // 4 threads per tile
    const int threads = 128;
    const int blocks = (nthr + threads - 1) / threads;
    jpeg_fused_kernel<<<blocks, threads>>>(in, out, nthr);
}